// round 13
// baseline (speedup 1.0000x reference)
#include <cuda_runtime.h>
#include <cuda_bf16.h>
#include <cstdint>
#include <cstddef>

#define N_NODES 20000
#define N_EDGES 4000
#define DIM     768
#define HIDW    1024
#define NO1     29
#define NO2     159

#define BM 128
#define BN 256
#define BK 64
#define NSTG 3
#define ABYTES (BM * BK * 2)
#define BBYTES (BN * BK * 2)
#define STGB   (ABYTES + BBYTES)
#define DSMEM  (NSTG * STGB)
#define YSPLIT 4
#define YSLICE ((size_t)DIM * N_EDGES)

__device__ __align__(128) __nv_bfloat16 g_Hbf [(size_t)N_NODES * N_EDGES];
__device__ __align__(128) __nv_bfloat16 g_HTbf[(size_t)N_EDGES * N_NODES];
__device__ __align__(128) __nv_bfloat16 g_Xbf [(size_t)N_NODES * DIM];
__device__ __align__(128) __nv_bfloat16 g_xtT [(size_t)DIM * N_NODES];
__device__ __align__(128) __nv_bfloat16 g_yT  [(size_t)DIM * N_EDGES];
__device__ __align__(128) float         g_ws  [YSPLIT * YSLICE];   // split-K workspace
__device__ __align__(128) float         g_Xn  [(size_t)N_NODES * DIM];
__device__ __align__(128) __nv_bfloat16 g_mlpA[(size_t)N_NODES * 2304];
__device__ __align__(128) __nv_bfloat16 g_th1T[DIM * DIM];
__device__ __align__(128) __nv_bfloat16 g_th2T[DIM * DIM];
__device__ __align__(128) __nv_bfloat16 g_W1Tp[(size_t)HIDW * 2304];
__device__ __align__(128) __nv_bfloat16 g_W2ap[32 * 1536];
__device__ __align__(128) __nv_bfloat16 g_W2bp[160 * 1536];
__device__ __align__(128) __nv_bfloat16 g_tA  [(size_t)N_NODES * 1536];
__device__ __align__(128) __nv_bfloat16 g_tB  [(size_t)N_NODES * 1536];
__device__ float g_dvsum [N_NODES];
__device__ float g_inv_dv[N_NODES];
__device__ float g_desum [N_EDGES];
__device__ float g_inv_de[N_EDGES];
__device__ float g_g1v[N_NODES];
__device__ float g_g2v[N_NODES];
__device__ float g_Pv[DIM];
__device__ float g_Sv[DIM];
__device__ float g_cvec[HIDW];

__device__ __forceinline__ uint32_t smem_u32(const void* p) {
    return (uint32_t)__cvta_generic_to_shared(p);
}
__device__ __forceinline__ void cp16(uint32_t dst, const void* src, int bytes) {
    asm volatile("cp.async.cg.shared.global [%0], [%1], 16, %2;\n"
                 :: "r"(dst), "l"(src), "r"(bytes));
}
__device__ __forceinline__ void cp_commit() { asm volatile("cp.async.commit_group;\n"); }
template <int NN>
__device__ __forceinline__ void cp_wait() { asm volatile("cp.async.wait_group %0;\n" :: "n"(NN)); }

__device__ __forceinline__ void ldsm4(uint32_t* r, uint32_t addr) {
    asm volatile("ldmatrix.sync.aligned.m8n8.x4.shared.b16 {%0,%1,%2,%3}, [%4];"
                 : "=r"(r[0]), "=r"(r[1]), "=r"(r[2]), "=r"(r[3]) : "r"(addr));
}
__device__ __forceinline__ void mma16816(float* c, const uint32_t* a, const uint32_t* b) {
    asm volatile("mma.sync.aligned.m16n8k16.row.col.f32.bf16.bf16.f32 "
                 "{%0,%1,%2,%3}, {%4,%5,%6,%7}, {%8,%9}, {%0,%1,%2,%3};\n"
                 : "+f"(c[0]), "+f"(c[1]), "+f"(c[2]), "+f"(c[3])
                 : "r"(a[0]), "r"(a[1]), "r"(a[2]), "r"(a[3]), "r"(b[0]), "r"(b[1]));
}

// D[M,Nc] = A[M,K] @ B[Nc,K]^T, both K-major bf16.
// Warp tile 64x64 (8 warps, BM=128 x BN=256), 1 CTA/SM, 3-stage cp.async pipeline.
// mode 0: bf16 out; 1: bf16(v*colvec[gc]); 2: Xn epilogue; 3: tanh split;
// mode 4: f32 v+colvec (gc<ncut); 5: raw f32 store (split-K partial).
// ksplit>0: blockIdx.z selects the K-slice; outf advances by z*M*ldo.
__global__ void __launch_bounds__(256)
tc_gemm(const __nv_bfloat16* __restrict__ A, int lda,
        const __nv_bfloat16* __restrict__ B, int ldb,
        int M, int Nc, int K, int mode,
        const float* __restrict__ rowscale, const float* __restrict__ colvec,
        const float* __restrict__ addf32,
        float* __restrict__ outf, __nv_bfloat16* __restrict__ outb,
        __nv_bfloat16* __restrict__ aux, __nv_bfloat16* __restrict__ aux2,
        int ldo, int ncut, int ksplit)
{
    extern __shared__ __align__(1024) char dsm[];
    const int tid = threadIdx.x;
    const int wid = tid >> 5;
    const int lane = tid & 31;
    const int wm = wid & 1;        // 2 warps over M: 64 rows each
    const int wn = wid >> 1;       // 4 warps over N: 64 cols each
    const int m0 = blockIdx.y * BM;
    const int n0 = blockIdx.x * BN;
    const uint32_t smb = smem_u32(dsm);

    if (ksplit > 0) {
        const int z = blockIdx.z;
        A += (size_t)z * ksplit;
        B += (size_t)z * ksplit;
        outf += (size_t)z * M * ldo;
        K = ksplit;
    }

    float acc[4][8][4];
#pragma unroll
    for (int i = 0; i < 4; i++)
#pragma unroll
        for (int j = 0; j < 8; j++)
#pragma unroll
            for (int r = 0; r < 4; r++) acc[i][j][r] = 0.f;

    const int nch = (K + BK - 1) / BK;

    auto load_stage = [&](int c) {
        const int slot = c % NSTG;
        const uint32_t ab = smb + slot * STGB;
        const uint32_t bb = ab + ABYTES;
        const int kb0 = c * BK;
#pragma unroll
        for (int i = 0; i < 4; i++) {
            int idx = tid + i * 256;
            int row = idx >> 3, ch = idx & 7;
            int gr = m0 + row, kel = kb0 + ch * 8;
            int bytes = (gr < M && kel < K) ? 16 : 0;
            const __nv_bfloat16* src = A + (size_t)(gr < M ? gr : 0) * lda + (kel < K ? kel : 0);
            uint32_t off = row * 128 + ch * 16;
            cp16(ab + (off ^ ((off >> 3) & 0x70)), src, bytes);
        }
#pragma unroll
        for (int i = 0; i < 8; i++) {
            int idx = tid + i * 256;
            int row = idx >> 3, ch = idx & 7;
            int gr = n0 + row, kel = kb0 + ch * 8;
            int bytes = (gr < Nc && kel < K) ? 16 : 0;
            const __nv_bfloat16* src = B + (size_t)(gr < Nc ? gr : 0) * ldb + (kel < K ? kel : 0);
            uint32_t off = row * 128 + ch * 16;
            cp16(bb + (off ^ ((off >> 3) & 0x70)), src, bytes);
        }
    };

    load_stage(0); cp_commit();
    if (nch > 1) load_stage(1);
    cp_commit();

    const int lr = ((lane >> 3) & 1) * 8 + (lane & 7);
    const int lk = (lane >> 4) * 16;

    // single-barrier mainloop (validated R12)
    for (int k = 0; k < nch; k++) {
        cp_wait<1>();
        __syncthreads();
        if (k + 2 < nch) load_stage(k + 2);
        cp_commit();
        const int slot = k % NSTG;
        const uint32_t ab = smb + slot * STGB;
        const uint32_t bb = ab + ABYTES;
#pragma unroll
        for (int ks = 0; ks < 4; ks++) {
            const int kbyte = ks * 32;
            // B first: 4 ldsm4 cover 64 cols
            uint32_t bfr[8][2];
#pragma unroll
            for (int j4 = 0; j4 < 4; j4++) {
                int row = wn * 64 + j4 * 16 + lr;
                uint32_t off = row * 128 + kbyte + lk;
                uint32_t t[4];
                ldsm4(t, bb + (off ^ ((off >> 3) & 0x70)));
                bfr[j4 * 2][0] = t[0]; bfr[j4 * 2 + 1][0] = t[1];
                bfr[j4 * 2][1] = t[2]; bfr[j4 * 2 + 1][1] = t[3];
            }
            uint32_t afr[4][4];
#pragma unroll
            for (int im = 0; im < 4; im++) {
                int row = wm * 64 + im * 16 + lr;
                uint32_t off = row * 128 + kbyte + lk;
                ldsm4(afr[im], ab + (off ^ ((off >> 3) & 0x70)));
            }
#pragma unroll
            for (int im = 0; im < 4; im++)
#pragma unroll
                for (int jn = 0; jn < 8; jn++)
                    mma16816(acc[im][jn], afr[im], bfr[jn]);
        }
    }

    const int g = lane >> 2, tg = lane & 3;
#pragma unroll
    for (int im = 0; im < 4; im++)
#pragma unroll
        for (int jn = 0; jn < 8; jn++)
#pragma unroll
            for (int r = 0; r < 4; r++) {
                int gr = m0 + wm * 64 + im * 16 + g + ((r >> 1) << 3);
                int gc = n0 + wn * 64 + jn * 8 + tg * 2 + (r & 1);
                if (gr >= M || gc >= Nc) continue;
                float v = acc[im][jn][r];
                if (mode == 0) {
                    outb[(size_t)gr * ldo + gc] = __float2bfloat16(v);
                } else if (mode == 1) {
                    outb[(size_t)gr * ldo + gc] = __float2bfloat16(v * colvec[gc]);
                } else if (mode == 2) {
                    v = v * rowscale[gr] + colvec[gc];
                    v = v > 0.f ? v : 0.01f * v;
                    v += addf32[(size_t)gr * DIM + gc];
                    outf[(size_t)gr * DIM + gc] = v;
                    __nv_bfloat16 h = __float2bfloat16(v);
                    __nv_bfloat16 l = __float2bfloat16(v - __bfloat162float(h));
                    size_t base = (size_t)gr * 2304;
                    aux[base + gc] = h;
                    aux[base + 768 + gc] = l;
                    aux[base + 1536 + gc] = h;
                } else if (mode == 3) {
                    float t = tanhf(v + colvec[gc]);
                    __nv_bfloat16 h = __float2bfloat16(t);
                    __nv_bfloat16 l = __float2bfloat16(t - __bfloat162float(h));
                    __nv_bfloat16* dst = (gc < 512) ? aux : aux2;
                    int c2 = (gc < 512) ? gc : gc - 512;
                    size_t base = (size_t)gr * 1536;
                    dst[base + c2] = h;
                    dst[base + 512 + c2] = l;
                    dst[base + 1024 + c2] = h;
                } else if (mode == 4) {
                    if (gc < ncut) outf[(size_t)gr * ldo + gc] = v + colvec[gc];
                } else { // mode 5
                    outf[(size_t)gr * ldo + gc] = v;
                }
            }
}

// ---------------- small kernels ----------------
__global__ void k_zero(float* p, int n) {
    int i = blockIdx.x * blockDim.x + threadIdx.x;
    if (i < n) p[i] = 0.f;
}
__global__ void k_recip(const float* a, float* b, int n) {
    int i = blockIdx.x * blockDim.x + threadIdx.x;
    if (i < n) b[i] = 1.f / a[i];
}
// deterministic split-K reduce: yT = bf16((p0+p1+p2+p3) * inv_de[col]); 2 elems/thread
__global__ void k_yred(const float* __restrict__ ws, __nv_bfloat16* __restrict__ yT) {
    int i = (blockIdx.x * blockDim.x + threadIdx.x) * 2;
    if (i >= (int)YSLICE) return;
    const float2 a = *(const float2*)(ws + i);
    const float2 b = *(const float2*)(ws + i + YSLICE);
    const float2 c = *(const float2*)(ws + i + 2 * YSLICE);
    const float2 d = *(const float2*)(ws + i + 3 * YSLICE);
    int col = i % N_EDGES;               // N_EDGES even: pair stays in one row
    float v0 = (a.x + b.x + c.x + d.x) * g_inv_de[col];
    float v1 = (a.y + b.y + c.y + d.y) * g_inv_de[col + 1];
    __nv_bfloat162 o;
    o.x = __float2bfloat16(v0);
    o.y = __float2bfloat16(v1);
    *(__nv_bfloat162*)(yT + i) = o;
}
// fused: convert H -> Hbf + HTbf AND accumulate row/col degree sums
__global__ void k_Hcvt(const float* __restrict__ H, float* __restrict__ dvsum,
                       float* __restrict__ desum) {
    __shared__ float t[32][33];
    int c0 = blockIdx.x * 32, r0 = blockIdx.y * 32;
    int tx = threadIdx.x, ty = threadIdx.y;
#pragma unroll
    for (int i = 0; i < 4; i++) {
        int r = r0 + ty + i * 8, c = c0 + tx;
        float v = H[(size_t)r * N_EDGES + c];
        g_Hbf[(size_t)r * N_EDGES + c] = __float2bfloat16(v);
        t[ty + i * 8][tx] = v;
    }
    __syncthreads();
#pragma unroll
    for (int i = 0; i < 4; i++) {
        int c = c0 + ty + i * 8, r = r0 + tx;
        g_HTbf[(size_t)c * N_NODES + r] = __float2bfloat16(t[tx][ty + i * 8]);
    }
    if (ty == 0) {
        float s = 0.f;
#pragma unroll
        for (int c = 0; c < 32; c++) s += t[tx][c];
        atomicAdd(&dvsum[r0 + tx], s);
    } else if (ty == 1) {
        float s = 0.f;
#pragma unroll
        for (int r = 0; r < 32; r++) s += t[r][tx];
        atomicAdd(&desum[c0 + tx], s);
    }
}
// vectorized f32 -> bf16 convert, 4 elems/thread (n must be multiple of 4)
__global__ void k_cvt4(const float* __restrict__ s, __nv_bfloat16* __restrict__ d, int n) {
    int i = (blockIdx.x * blockDim.x + threadIdx.x) * 4;
    if (i >= n) return;
    const float4 v = *(const float4*)(s + i);
    __nv_bfloat162 lo, hi;
    lo.x = __float2bfloat16(v.x); lo.y = __float2bfloat16(v.y);
    hi.x = __float2bfloat16(v.z); hi.y = __float2bfloat16(v.w);
    *(__nv_bfloat162*)(d + i) = lo;
    *(__nv_bfloat162*)(d + i + 2) = hi;
}
__global__ void k_tcvt(const float* __restrict__ src, __nv_bfloat16* __restrict__ dst,
                       int R, int C) {
    __shared__ float t[32][33];
    int c0 = blockIdx.x * 32, r0 = blockIdx.y * 32;
    int tx = threadIdx.x, ty = threadIdx.y;
#pragma unroll
    for (int i = 0; i < 4; i++)
        t[ty + i * 8][tx] = src[(size_t)(r0 + ty + i * 8) * C + c0 + tx];
    __syncthreads();
#pragma unroll
    for (int i = 0; i < 4; i++)
        dst[(size_t)(c0 + ty + i * 8) * R + r0 + tx] = __float2bfloat16(t[tx][ty + i * 8]);
}
__global__ void k_W1Tp(const float* __restrict__ W1a, const float* __restrict__ W1b) {
    int idx = blockIdx.x * blockDim.x + threadIdx.x;
    if (idx >= HIDW * DIM) return;
    int h = idx / DIM, d = idx % DIM;
    float v = (h < 512) ? W1a[d * 512 + h] : W1b[d * 512 + (h - 512)];
    __nv_bfloat16 hi = __float2bfloat16(v);
    __nv_bfloat16 lo = __float2bfloat16(v - __bfloat162float(hi));
    size_t base = (size_t)h * 2304;
    g_W1Tp[base + d] = hi;
    g_W1Tp[base + 768 + d] = hi;
    g_W1Tp[base + 1536 + d] = lo;
}
__global__ void k_W2p(const float* __restrict__ W2, __nv_bfloat16* __restrict__ dst,
                      int NO, int NP) {
    int idx = blockIdx.x * blockDim.x + threadIdx.x;
    if (idx >= NP * 512) return;
    int n = idx / 512, kk = idx % 512;
    float v = (n < NO) ? W2[kk * NO + n] : 0.f;
    __nv_bfloat16 hi = __float2bfloat16(v);
    __nv_bfloat16 lo = __float2bfloat16(v - __bfloat162float(hi));
    size_t base = (size_t)n * 1536;
    dst[base + kk] = hi;
    dst[base + 512 + kk] = hi;
    dst[base + 1024 + kk] = lo;
}
__global__ void k_gmean(const float* __restrict__ G, int rows, float* __restrict__ out) {
    int c = blockIdx.x * blockDim.x + threadIdx.x;
    if (c >= N_NODES) return;
    float s = 0.f;
    for (int r = 0; r < rows; r++) s += G[(size_t)r * N_NODES + c];
    out[c] = s / (float)rows;
}
__global__ void k_PS(const float* __restrict__ Xn) {
    int sub = threadIdx.x >> 5, c = threadIdx.x & 31;
    int d = blockIdx.x * 32 + c;
    float p = 0.f, s = 0.f;
    for (int r = sub; r < N_NODES; r += 8) {
        float x = Xn[(size_t)r * DIM + d];
        p += g_g1v[r] * x;
        s += g_g2v[r] * x;
    }
    __shared__ float sp[8][32], ss[8][32];
    sp[sub][c] = p; ss[sub][c] = s;
    __syncthreads();
    if (sub == 0) {
        float tp = 0.f, ts = 0.f;
#pragma unroll
        for (int i = 0; i < 8; i++) { tp += sp[i][c]; ts += ss[i][c]; }
        g_Pv[d] = tp; g_Sv[d] = ts;
    }
}
__global__ void k_cvec(const float* __restrict__ W1a, const float* __restrict__ b1a,
                       const float* __restrict__ W1b, const float* __restrict__ b1b) {
    int h = blockIdx.x * blockDim.x + threadIdx.x;
    if (h >= HIDW) return;
    float s;
    if (h < 512) {
        s = b1a[h];
        for (int d = 0; d < DIM; d++) s += g_Pv[d] * W1a[(768 + d) * 512 + h];
    } else {
        int hh = h - 512;
        s = b1b[hh];
        for (int d = 0; d < DIM; d++) s += g_Sv[d] * W1b[(768 + d) * 512 + hh];
    }
    g_cvec[h] = s;
}

// ---------------- host ----------------
static inline void launch_gemm(const __nv_bfloat16* A, int lda,
                               const __nv_bfloat16* B, int ldb,
                               int M, int Nc, int K, int mode,
                               const float* rs, const float* cv, const float* add,
                               float* outf, __nv_bfloat16* outb,
                               __nv_bfloat16* aux, __nv_bfloat16* aux2,
                               int ldo, int ncut, int ksplit = 0, int gz = 1)
{
    dim3 grid((Nc + BN - 1) / BN, (M + BM - 1) / BM, gz);
    tc_gemm<<<grid, 256, DSMEM>>>(A, lda, B, ldb, M, Nc, K, mode,
                                  rs, cv, add, outf, outb, aux, aux2, ldo, ncut, ksplit);
}

extern "C" void kernel_launch(void* const* d_in, const int* in_sizes, int n_in,
                              void* d_out, int out_size)
{
    const float* X   = (const float*)d_in[0];
    const float* H   = (const float*)d_in[1];
    const float* G2  = (const float*)d_in[2];
    const float* G1  = (const float*)d_in[3];
    const float* th1 = (const float*)d_in[4];
    const float* b1  = (const float*)d_in[5];
    const float* th2 = (const float*)d_in[6];
    const float* b2  = (const float*)d_in[7];
    const float* W1a = (const float*)d_in[8];
    const float* b1a = (const float*)d_in[9];
    const float* W2a = (const float*)d_in[10];
    const float* b2a = (const float*)d_in[11];
    const float* W1b = (const float*)d_in[12];
    const float* b1b = (const float*)d_in[13];
    const float* W2b = (const float*)d_in[14];
    const float* b2b = (const float*)d_in[15];
    float* out = (float*)d_out;

    cudaFuncSetAttribute(tc_gemm, cudaFuncAttributeMaxDynamicSharedMemorySize, DSMEM);

    __nv_bfloat16 *Hbf, *HTbf, *Xbf, *xtT, *yT, *mlpA, *th1T, *th2T, *W1Tp, *W2ap, *W2bp, *tA, *tB;
    float *Xn, *ws, *dvsum, *inv_dv, *desum, *inv_de, *g1v, *g2v, *cvec;
    cudaGetSymbolAddress((void**)&Hbf,  g_Hbf);
    cudaGetSymbolAddress((void**)&HTbf, g_HTbf);
    cudaGetSymbolAddress((void**)&Xbf,  g_Xbf);
    cudaGetSymbolAddress((void**)&xtT,  g_xtT);
    cudaGetSymbolAddress((void**)&yT,   g_yT);
    cudaGetSymbolAddress((void**)&ws,   g_ws);
    cudaGetSymbolAddress((void**)&Xn,   g_Xn);
    cudaGetSymbolAddress((void**)&mlpA, g_mlpA);
    cudaGetSymbolAddress((void**)&th1T, g_th1T);
    cudaGetSymbolAddress((void**)&th2T, g_th2T);
    cudaGetSymbolAddress((void**)&W1Tp, g_W1Tp);
    cudaGetSymbolAddress((void**)&W2ap, g_W2ap);
    cudaGetSymbolAddress((void**)&W2bp, g_W2bp);
    cudaGetSymbolAddress((void**)&tA,   g_tA);
    cudaGetSymbolAddress((void**)&tB,   g_tB);
    cudaGetSymbolAddress((void**)&dvsum,  g_dvsum);
    cudaGetSymbolAddress((void**)&inv_dv, g_inv_dv);
    cudaGetSymbolAddress((void**)&desum,  g_desum);
    cudaGetSymbolAddress((void**)&inv_de, g_inv_de);
    cudaGetSymbolAddress((void**)&g1v, g_g1v);
    cudaGetSymbolAddress((void**)&g2v, g_g2v);
    cudaGetSymbolAddress((void**)&cvec, g_cvec);

    // slots 1-3: minimal deps for GEMM1; slot 4 = GEMM1 (ncu window lands on tc_gemm)
    k_cvt4<<<(N_NODES * DIM / 4 + 255) / 256, 256>>>(X, Xbf, N_NODES * DIM);   // 1
    k_tcvt<<<dim3(DIM / 32, DIM / 32), dim3(32, 8)>>>(th1, th1T, DIM, DIM);    // 2
    k_zero<<<(N_NODES + 255) / 256, 256>>>(dvsum, N_NODES);                    // 3
    launch_gemm(th1T, DIM, Xbf, DIM, DIM, N_NODES, DIM, 0,                     // 4: xtT = th1T @ X^T
                nullptr, nullptr, nullptr, nullptr, xtT, nullptr, nullptr, N_NODES, 0);
    k_zero<<<(N_EDGES + 255) / 256, 256>>>(desum, N_EDGES);                    // 5
    k_Hcvt<<<dim3(N_EDGES / 32, N_NODES / 32), dim3(32, 8)>>>(H, dvsum, desum);// 6
    k_recip<<<(N_EDGES + 255) / 256, 256>>>(desum, inv_de, N_EDGES);
    k_recip<<<(N_NODES + 255) / 256, 256>>>(dvsum, inv_dv, N_NODES);

    // GEMM2 split-K=4: partials -> ws ; reduce -> yT (scaled by inv_de)
    launch_gemm(xtT, N_NODES, HTbf, N_NODES, DIM, N_EDGES, N_NODES, 5,
                nullptr, nullptr, nullptr, ws, nullptr, nullptr, nullptr, N_EDGES, 0,
                N_NODES / YSPLIT, YSPLIT);
    k_yred<<<((int)YSLICE / 2 + 255) / 256, 256>>>(ws, yT);
    // GEMM3: Xn = leaky(H @ yT^T * inv_dv + b1) + X  (+ mlpA hi/lo/hi)
    launch_gemm(Hbf, N_EDGES, yT, N_EDGES, N_NODES, DIM, N_EDGES, 2,
                inv_dv, b1, X, Xn, nullptr, mlpA, nullptr, DIM, 0);

    // round 2
    k_tcvt<<<dim3(DIM / 32, DIM / 32), dim3(32, 8)>>>(th2, th2T, DIM, DIM);
    launch_gemm(th2T, DIM, mlpA, 2304, DIM, N_NODES, DIM, 0,
                nullptr, nullptr, nullptr, nullptr, xtT, nullptr, nullptr, N_NODES, 0);
    launch_gemm(xtT, N_NODES, HTbf, N_NODES, DIM, N_EDGES, N_NODES, 5,
                nullptr, nullptr, nullptr, ws, nullptr, nullptr, nullptr, N_EDGES, 0,
                N_NODES / YSPLIT, YSPLIT);
    k_yred<<<((int)YSLICE / 2 + 255) / 256, 256>>>(ws, yT);
    launch_gemm(Hbf, N_EDGES, yT, N_EDGES, N_NODES, DIM, N_EDGES, 2,
                inv_dv, b2, X, Xn, nullptr, mlpA, nullptr, DIM, 0);

    // pooled vectors + constant hidden bias
    k_gmean<<<(N_NODES + 255) / 256, 256>>>(G2, 512, g2v);
    k_gmean<<<(N_NODES + 255) / 256, 256>>>(G1, 128, g1v);
    k_PS<<<DIM / 32, 256>>>(Xn);
    k_cvec<<<(HIDW + 255) / 256, 256>>>(W1a, b1a, W1b, b1b);

    // hidden: tanh(Xn@W1 + cvec), split bf16 via tripled K
    k_W1Tp<<<(HIDW * DIM + 255) / 256, 256>>>(W1a, W1b);
    launch_gemm(mlpA, 2304, W1Tp, 2304, N_NODES, HIDW, 2304, 3,
                nullptr, cvec, nullptr, nullptr, nullptr, tA, tB, 0, 0);

    // heads
    k_W2p<<<(32 * 512 + 255) / 256, 256>>>(W2a, W2ap, NO1, 32);
    k_W2p<<<(160 * 512 + 255) / 256, 256>>>(W2b, W2bp, NO2, 160);
    float* o1 = out;
    float* o2 = out + (size_t)N_NODES * NO1;
    launch_gemm(tA, 1536, W2ap, 1536, N_NODES, 32, 1536, 4,
                nullptr, b2a, nullptr, o1, nullptr, nullptr, nullptr, NO1, NO1);
    launch_gemm(tB, 1536, W2bp, 1536, N_NODES, 160, 1536, 4,
                nullptr, b2b, nullptr, o2, nullptr, nullptr, nullptr, NO2, NO2);
}